// round 1
// baseline (speedup 1.0000x reference)
#include <cuda_runtime.h>
#include <cuda_bf16.h>
#include <math_constants.h>

// Problem constants
#define NNODES 50000
#define NEDGES 800000
#define NEALL  (NEDGES + NNODES)   // edges + self loops
#define NGRAPH 64
#define DMAX   256
#define HID    512

// ---------------- scratch (no allocations allowed) ----------------
__device__ float g_bufA[(size_t)NNODES * DMAX];  // h = x @ W
__device__ float g_bufB[(size_t)NNODES * DMAX];  // aggregated out
__device__ float g_bufC[(size_t)NNODES * DMAX];  // layer input/output (relu'd)
__device__ float g_logit[NEALL];                 // per-edge logit, then exp (in-place)
__device__ float g_m[NNODES];                    // segment max
__device__ float g_s[NNODES];                    // segment sum
__device__ float g_as[NNODES];                   // h . att_src
__device__ float g_ad[NNODES];                   // h . att_dst

// ---------------- helpers ----------------
__device__ __forceinline__ void atomicMaxF(float* addr, float v) {
    if (v >= 0.f) atomicMax((int*)addr, __float_as_int(v));
    else          atomicMin((unsigned int*)addr, (unsigned int)__float_as_int(v));
}

__device__ __forceinline__ void red_add_v4(float* addr, float4 v) {
    asm volatile("red.global.add.v4.f32 [%0], {%1,%2,%3,%4};"
                 :: "l"(addr), "f"(v.x), "f"(v.y), "f"(v.z), "f"(v.w) : "memory");
}

// ---------------- kernels ----------------

// zero out[0..nd), m = -inf, s = 0 for [0..n)
__global__ void zero_kernel(float* out, size_t nd, float* m, float* s, int n) {
    size_t i = (size_t)blockIdx.x * blockDim.x + threadIdx.x;
    size_t stride = (size_t)gridDim.x * blockDim.x;
    for (size_t k = i; k < nd; k += stride) out[k] = 0.f;
    for (size_t k = i; k < (size_t)n; k += stride) {
        m[k] = -CUDART_INF_F;
        s[k] = 0.f;
    }
}

// C[M,Nd] = A[M,K] @ B[K,Nd].  BM=64, BN=64, BK=16, 256 thr, 4x4 microtile.
// Requires: K % 16 == 0, Nd % 64 == 0 (true: K in {64,128}, Nd in {64,128,256}).
#define BM 64
#define BN 64
#define BK 16
#define BMP (BM + 4)
__global__ void sgemm_kernel(const float* __restrict__ A, const float* __restrict__ B,
                             float* __restrict__ C, int M, int Nd, int K) {
    __shared__ float As[BK][BMP];   // transposed A tile
    __shared__ float Bs[BK][BN];
    const int tid = threadIdx.x;
    const int tx = tid & 15;        // 0..15 -> cols (x4)
    const int ty = tid >> 4;        // 0..15 -> rows (x4)
    const int row0 = blockIdx.x * BM;
    const int col0 = blockIdx.y * BN;

    const int aM  = tid >> 2;        // 0..63
    const int aK4 = (tid & 3) << 2;  // 0,4,8,12
    const int bK  = tid >> 4;        // 0..15
    const int bN4 = (tid & 15) << 2; // 0..60

    float acc[4][4];
#pragma unroll
    for (int i = 0; i < 4; i++)
#pragma unroll
        for (int j = 0; j < 4; j++) acc[i][j] = 0.f;

    for (int k0 = 0; k0 < K; k0 += BK) {
        float4 av = make_float4(0.f, 0.f, 0.f, 0.f);
        int gr = row0 + aM;
        if (gr < M) av = *(const float4*)(A + (size_t)gr * K + k0 + aK4);
        As[aK4 + 0][aM] = av.x;
        As[aK4 + 1][aM] = av.y;
        As[aK4 + 2][aM] = av.z;
        As[aK4 + 3][aM] = av.w;
        *(float4*)&Bs[bK][bN4] = *(const float4*)(B + (size_t)(k0 + bK) * Nd + col0 + bN4);
        __syncthreads();
#pragma unroll
        for (int kk = 0; kk < BK; kk++) {
            float4 a = *(float4*)&As[kk][ty << 2];
            float4 b = *(float4*)&Bs[kk][tx << 2];
            float ar[4] = {a.x, a.y, a.z, a.w};
            float br[4] = {b.x, b.y, b.z, b.w};
#pragma unroll
            for (int i = 0; i < 4; i++)
#pragma unroll
                for (int j = 0; j < 4; j++) acc[i][j] += ar[i] * br[j];
        }
        __syncthreads();
    }
#pragma unroll
    for (int i = 0; i < 4; i++) {
        int gr = row0 + (ty << 2) + i;
        if (gr < M) {
            float4 v = make_float4(acc[i][0], acc[i][1], acc[i][2], acc[i][3]);
            *(float4*)(C + (size_t)gr * Nd + col0 + (tx << 2)) = v;
        }
    }
}

// as[n] = h[n,:].att[0,:], ad[n] = h[n,:].att[1,:]   (warp per node)
__global__ void attdot_kernel(const float* __restrict__ h, const float* __restrict__ att,
                              int n, int D, float* __restrict__ as_, float* __restrict__ ad_) {
    int w = (blockIdx.x * blockDim.x + threadIdx.x) >> 5;
    int lane = threadIdx.x & 31;
    if (w >= n) return;
    float a0 = 0.f, a1 = 0.f;
    const float* hr = h + (size_t)w * D;
    for (int d = lane; d < D; d += 32) {
        float hv = hr[d];
        a0 += hv * att[d];
        a1 += hv * att[D + d];
    }
#pragma unroll
    for (int o = 16; o; o >>= 1) {
        a0 += __shfl_xor_sync(0xffffffffu, a0, o);
        a1 += __shfl_xor_sync(0xffffffffu, a1, o);
    }
    if (lane == 0) { as_[w] = a0; ad_[w] = a1; }
}

// logit[e] = leaky_relu(as[src]+ad[dst], 0.2); m[dst] = max(m[dst], logit)
__global__ void edge_logit_kernel(const float* __restrict__ as_, const float* __restrict__ ad_,
                                  const int* __restrict__ ei, float* __restrict__ logit,
                                  float* __restrict__ m) {
    int e = blockIdx.x * blockDim.x + threadIdx.x;
    if (e >= NEALL) return;
    int s, d;
    if (e < NEDGES) { s = ei[e]; d = ei[NEDGES + e]; }
    else            { s = d = e - NEDGES; }
    float v = as_[s] + ad_[d];
    v = (v > 0.f) ? v : 0.2f * v;
    logit[e] = v;
    atomicMaxF(&m[d], v);
}

// logit[e] <- exp(logit[e]-m[dst]); s[dst] += it
__global__ void edge_exp_kernel(float* __restrict__ logit, const float* __restrict__ m,
                                float* __restrict__ s_, const int* __restrict__ ei) {
    int e = blockIdx.x * blockDim.x + threadIdx.x;
    if (e >= NEALL) return;
    int d = (e < NEDGES) ? ei[NEDGES + e] : (e - NEDGES);
    float ex = __expf(logit[e] - m[d]);
    logit[e] = ex;
    atomicAdd(&s_[d], ex);
}

// warp per edge: out[dst,:] += (e/s[dst]) * h[src,:]
__global__ void edge_scatter_kernel(const float* __restrict__ h, const float* __restrict__ ev,
                                    const float* __restrict__ s_, const int* __restrict__ ei,
                                    int D, float* __restrict__ out) {
    int w = (blockIdx.x * blockDim.x + threadIdx.x) >> 5;
    int lane = threadIdx.x & 31;
    if (w >= NEALL) return;
    int s, d;
    if (w < NEDGES) { s = ei[w]; d = ei[NEDGES + w]; }
    else            { s = d = w - NEDGES; }
    float coef = ev[w] / s_[d];
    const float4* hs = (const float4*)(h + (size_t)s * D);
    float* od = out + (size_t)d * D;
    int nv = D >> 2;
    for (int i = lane; i < nv; i += 32) {
        float4 v = hs[i];
        v.x *= coef; v.y *= coef; v.z *= coef; v.w *= coef;
        red_add_v4(od + 4 * i, v);
    }
}

// x[n,d] = relu(out[n,d] + b[d])
__global__ void bias_relu_kernel(const float* __restrict__ out, const float* __restrict__ b,
                                 size_t nd, int Dmask, float* __restrict__ x) {
    size_t i = (size_t)blockIdx.x * blockDim.x + threadIdx.x;
    size_t stride = (size_t)gridDim.x * blockDim.x;
    for (size_t k = i; k < nd; k += stride) {
        float v = out[k] + b[k & (size_t)Dmask];
        x[k] = fmaxf(v, 0.f);
    }
}

__device__ __forceinline__ int lbound(const int* a, int n, int key) {
    int lo = 0, hi = n;
    while (lo < hi) {
        int mid = (lo + hi) >> 1;
        if (a[mid] < key) lo = mid + 1; else hi = mid;
    }
    return lo;
}

// One block (256 thr) per graph: mean pool over sorted batch range, then 256->512->1 MLP.
__global__ void pool_mlp_kernel(const float* __restrict__ x, const int* __restrict__ batch,
                                const float* __restrict__ fc1w, const float* __restrict__ fc1b,
                                const float* __restrict__ fc2w, const float* __restrict__ fc2b,
                                float* __restrict__ out) {
    __shared__ float gc[DMAX];
    __shared__ float hid[HID];
    __shared__ float red[256];
    int g = blockIdx.x;
    int t = threadIdx.x;
    int lo = lbound(batch, NNODES, g);
    int hi = lbound(batch, NNODES, g + 1);
    float cnt = fmaxf((float)(hi - lo), 1.f);
    float acc = 0.f;
    for (int n = lo; n < hi; n++) acc += x[(size_t)n * DMAX + t];
    gc[t] = acc / cnt;
    __syncthreads();
    for (int c = t; c < HID; c += 256) {
        float a = fc1b[c];
#pragma unroll 8
        for (int k = 0; k < DMAX; k++) a += gc[k] * fc1w[(size_t)k * HID + c];
        hid[c] = fmaxf(a, 0.f);
    }
    __syncthreads();
    float p = 0.f;
    for (int c = t; c < HID; c += 256) p += hid[c] * fc2w[c];
    red[t] = p;
    __syncthreads();
    for (int s = 128; s; s >>= 1) {
        if (t < s) red[t] += red[t + s];
        __syncthreads();
    }
    if (t == 0) out[g] = red[0] + fc2b[0];
}

// ---------------- launcher ----------------
extern "C" void kernel_launch(void* const* d_in, const int* in_sizes, int n_in,
                              void* d_out, int out_size) {
    const float* feature = (const float*)d_in[0];
    const int*   ei      = (const int*)d_in[1];
    const int*   batch   = (const int*)d_in[2];
    const float* W[3]    = {(const float*)d_in[3], (const float*)d_in[6], (const float*)d_in[9]};
    const float* att[3]  = {(const float*)d_in[4], (const float*)d_in[7], (const float*)d_in[10]};
    const float* bia[3]  = {(const float*)d_in[5], (const float*)d_in[8], (const float*)d_in[11]};
    const float* fc1w    = (const float*)d_in[12];
    const float* fc1b    = (const float*)d_in[13];
    const float* fc2w    = (const float*)d_in[14];
    const float* fc2b    = (const float*)d_in[15];

    float *bufA, *bufB, *bufC, *logit, *mbuf, *sbuf, *asbuf, *adbuf;
    cudaGetSymbolAddress((void**)&bufA, g_bufA);
    cudaGetSymbolAddress((void**)&bufB, g_bufB);
    cudaGetSymbolAddress((void**)&bufC, g_bufC);
    cudaGetSymbolAddress((void**)&logit, g_logit);
    cudaGetSymbolAddress((void**)&mbuf, g_m);
    cudaGetSymbolAddress((void**)&sbuf, g_s);
    cudaGetSymbolAddress((void**)&asbuf, g_as);
    cudaGetSymbolAddress((void**)&adbuf, g_ad);

    const int Dout[3] = {64, 128, 256};
    int Din = 64;
    const float* x = feature;

    for (int l = 0; l < 3; l++) {
        int D = Dout[l];
        size_t nd = (size_t)NNODES * D;

        zero_kernel<<<2048, 256>>>(bufB, nd, mbuf, sbuf, NNODES);
        sgemm_kernel<<<dim3((NNODES + BM - 1) / BM, D / BN), 256>>>(x, W[l], bufA, NNODES, D, Din);
        attdot_kernel<<<(NNODES * 32 + 255) / 256, 256>>>(bufA, att[l], NNODES, D, asbuf, adbuf);
        edge_logit_kernel<<<(NEALL + 255) / 256, 256>>>(asbuf, adbuf, ei, logit, mbuf);
        edge_exp_kernel<<<(NEALL + 255) / 256, 256>>>(logit, mbuf, sbuf, ei);
        edge_scatter_kernel<<<((size_t)NEALL * 32 + 255) / 256, 256>>>(bufA, logit, sbuf, ei, D, bufB);
        bias_relu_kernel<<<2048, 256>>>(bufB, bia[l], nd, D - 1, bufC);

        x = bufC;
        Din = D;
    }

    pool_mlp_kernel<<<NGRAPH, 256>>>(bufC, batch, fc1w, fc1b, fc2w, fc2b, (float*)d_out);
}

// round 2
// speedup vs baseline: 2.9666x; 2.9666x over previous
#include <cuda_runtime.h>
#include <cuda_bf16.h>
#include <math_constants.h>

// Problem constants
#define NNODES 50000
#define NEDGES 800000
#define NEALL  (NEDGES + NNODES)   // edges + self loops
#define NGRAPH 64
#define DMAX   256
#define HID    512
#define NB     ((NNODES + 255) / 256)   // scan blocks = 196

// ---------------- scratch (no allocations allowed) ----------------
__device__ float g_bufA[(size_t)NNODES * DMAX];  // h = x @ W
__device__ float g_bufC[(size_t)NNODES * DMAX];  // layer output (relu'd)
__device__ int   g_csr[NEALL];                   // src node per CSR slot
__device__ int   g_cnt[NNODES];                  // in-degree
__device__ int   g_off[NNODES + 1];              // CSR offsets
__device__ int   g_cursor[NNODES];               // fill cursors
__device__ int   g_bsum[NB];                     // scan block sums
__device__ float g_as[NNODES];                   // x . (W att_src)
__device__ float g_ad[NNODES];                   // x . (W att_dst)
__device__ float g_wa[128];                      // W @ att_src
__device__ float g_wd[128];                      // W @ att_dst

// ---------------- CSR build ----------------
__global__ void zero_cnt_kernel(int* cnt) {
    int i = blockIdx.x * blockDim.x + threadIdx.x;
    if (i < NNODES) cnt[i] = 0;
}

__global__ void hist_kernel(const int* __restrict__ ei, int* __restrict__ cnt) {
    int e = blockIdx.x * blockDim.x + threadIdx.x;
    if (e >= NEALL) return;
    int d = (e < NEDGES) ? ei[NEDGES + e] : (e - NEDGES);
    atomicAdd(&cnt[d], 1);
}

__global__ void scan1_kernel(const int* __restrict__ cnt, int* __restrict__ off,
                             int* __restrict__ bsum) {
    __shared__ int sh[256];
    int t = threadIdx.x;
    int i = blockIdx.x * 256 + t;
    int v = (i < NNODES) ? cnt[i] : 0;
    sh[t] = v;
    __syncthreads();
#pragma unroll
    for (int o = 1; o < 256; o <<= 1) {
        int add = (t >= o) ? sh[t - o] : 0;
        __syncthreads();
        sh[t] += add;
        __syncthreads();
    }
    if (i < NNODES) off[i] = sh[t] - v;     // exclusive within block
    if (t == 255) bsum[blockIdx.x] = sh[255];
}

__global__ void scan2_kernel(int* __restrict__ bsum) {
    __shared__ int sh[256];
    int t = threadIdx.x;
    int v = (t < NB) ? bsum[t] : 0;
    sh[t] = v;
    __syncthreads();
#pragma unroll
    for (int o = 1; o < 256; o <<= 1) {
        int add = (t >= o) ? sh[t - o] : 0;
        __syncthreads();
        sh[t] += add;
        __syncthreads();
    }
    if (t < NB) bsum[t] = sh[t] - v;        // exclusive
}

__global__ void scan3_kernel(int* __restrict__ off, const int* __restrict__ bsum,
                             int* __restrict__ cursor) {
    int i = blockIdx.x * 256 + threadIdx.x;
    if (i < NNODES) {
        int o = off[i] + bsum[i >> 8];
        off[i] = o;
        cursor[i] = o;
    }
    if (i == 0) off[NNODES] = NEALL;
}

__global__ void csr_fill_kernel(const int* __restrict__ ei, int* __restrict__ cursor,
                                int* __restrict__ csr) {
    int e = blockIdx.x * blockDim.x + threadIdx.x;
    if (e >= NEALL) return;
    int s, d;
    if (e < NEDGES) { s = ei[e]; d = ei[NEDGES + e]; }
    else            { s = d = e - NEDGES; }
    int pos = atomicAdd(&cursor[d], 1);
    csr[pos] = s;
}

// ---------------- attention vector precompute ----------------
// wa[i] = sum_d W[i,d]*att[0,d]; wd[i] = sum_d W[i,d]*att[1,d]   (warp per output)
__global__ void wvec_kernel(const float* __restrict__ W, const float* __restrict__ att,
                            int Din, int Dout, float* __restrict__ wa, float* __restrict__ wd) {
    int w = (blockIdx.x * blockDim.x + threadIdx.x) >> 5;
    int lane = threadIdx.x & 31;
    int i = w >> 1, which = w & 1;
    if (i >= Din) return;
    const float* attp = att + which * Dout;
    const float* Wr = W + (size_t)i * Dout;
    float acc = 0.f;
    for (int d = lane; d < Dout; d += 32) acc += Wr[d] * attp[d];
#pragma unroll
    for (int o = 16; o; o >>= 1) acc += __shfl_xor_sync(0xffffffffu, acc, o);
    if (lane == 0) {
        if (which == 0) wa[i] = acc; else wd[i] = acc;
    }
}

// as[n] = x[n,:].wa, ad[n] = x[n,:].wd     (warp per node, Din in {64,128})
__global__ void attdot_x_kernel(const float* __restrict__ x, const float* __restrict__ wa,
                                const float* __restrict__ wd, int Din,
                                float* __restrict__ as_, float* __restrict__ ad_) {
    int w = (blockIdx.x * blockDim.x + threadIdx.x) >> 5;
    int lane = threadIdx.x & 31;
    if (w >= NNODES) return;
    const float* xr = x + (size_t)w * Din;
    float a0 = 0.f, a1 = 0.f;
    for (int d = lane; d < Din; d += 32) {
        float xv = xr[d];
        a0 += xv * wa[d];
        a1 += xv * wd[d];
    }
#pragma unroll
    for (int o = 16; o; o >>= 1) {
        a0 += __shfl_xor_sync(0xffffffffu, a0, o);
        a1 += __shfl_xor_sync(0xffffffffu, a1, o);
    }
    if (lane == 0) { as_[w] = a0; ad_[w] = a1; }
}

// ---------------- SGEMM: C[M,Nd] = A[M,K] @ B[K,Nd] ----------------
// BM=128, BN=64, BK=16, 256 threads, 8x4 microtile. K%16==0, Nd%64==0.
#define GBM 128
#define GBN 64
#define GBK 16
#define GBMP (GBM + 4)
__global__ __launch_bounds__(256) void sgemm_kernel(const float* __restrict__ A,
                                                    const float* __restrict__ B,
                                                    float* __restrict__ C,
                                                    int M, int Nd, int K) {
    __shared__ float As[GBK][GBMP];
    __shared__ float Bs[GBK][GBN];
    const int tid = threadIdx.x;
    const int tx = tid & 15;         // 16 col groups x4
    const int ty = tid >> 4;         // 16 row groups x8
    const int row0 = blockIdx.x * GBM;
    const int col0 = blockIdx.y * GBN;

    float acc[8][4];
#pragma unroll
    for (int i = 0; i < 8; i++)
#pragma unroll
        for (int j = 0; j < 4; j++) acc[i][j] = 0.f;

    const int br = tid >> 4;          // 0..15
    const int bc = (tid & 15) << 2;   // 0..60

    for (int k0 = 0; k0 < K; k0 += GBK) {
#pragma unroll
        for (int i = 0; i < 2; i++) {
            int linear = tid + 256 * i;          // 0..511 float4 slots
            int ar = linear >> 2;                // 0..127
            int ac = (linear & 3) << 2;          // 0,4,8,12
            int gr = row0 + ar;
            float4 v = make_float4(0.f, 0.f, 0.f, 0.f);
            if (gr < M) v = *(const float4*)(A + (size_t)gr * K + k0 + ac);
            As[ac + 0][ar] = v.x;
            As[ac + 1][ar] = v.y;
            As[ac + 2][ar] = v.z;
            As[ac + 3][ar] = v.w;
        }
        *(float4*)&Bs[br][bc] = *(const float4*)(B + (size_t)(k0 + br) * Nd + col0 + bc);
        __syncthreads();
#pragma unroll
        for (int kk = 0; kk < GBK; kk++) {
            float4 a0 = *(float4*)&As[kk][ty * 8];
            float4 a1 = *(float4*)&As[kk][ty * 8 + 4];
            float4 b  = *(float4*)&Bs[kk][tx * 4];
            float ar8[8] = {a0.x, a0.y, a0.z, a0.w, a1.x, a1.y, a1.z, a1.w};
            float br4[4] = {b.x, b.y, b.z, b.w};
#pragma unroll
            for (int i = 0; i < 8; i++)
#pragma unroll
                for (int j = 0; j < 4; j++) acc[i][j] += ar8[i] * br4[j];
        }
        __syncthreads();
    }
#pragma unroll
    for (int i = 0; i < 8; i++) {
        int gr = row0 + ty * 8 + i;
        if (gr < M) {
            float4 v = make_float4(acc[i][0], acc[i][1], acc[i][2], acc[i][3]);
            *(float4*)(C + (size_t)gr * Nd + col0 + tx * 4) = v;
        }
    }
}

// ---------------- fused GAT aggregation (gather) ----------------
// warp per dst node: softmax over incoming edges + weighted gather + bias + relu
template <int D>
__global__ __launch_bounds__(256) void gat_aggregate_kernel(
    const float* __restrict__ h, const float* __restrict__ as_,
    const float* __restrict__ ad_, const int* __restrict__ off,
    const int* __restrict__ csr, const float* __restrict__ bias,
    float* __restrict__ out) {
    int w = (blockIdx.x * blockDim.x + threadIdx.x) >> 5;
    int lane = threadIdx.x & 31;
    if (w >= NNODES) return;
    int lo = off[w], hi = off[w + 1];
    float adv = ad_[w];

    // pass 1: segment max of leaky_relu(as[src]+ad[dst])
    float mx = -CUDART_INF_F;
    for (int e = lo + lane; e < hi; e += 32) {
        float v = as_[csr[e]] + adv;
        v = (v > 0.f) ? v : 0.2f * v;
        mx = fmaxf(mx, v);
    }
#pragma unroll
    for (int o = 16; o; o >>= 1) mx = fmaxf(mx, __shfl_xor_sync(0xffffffffu, mx, o));

    // pass 2: weighted accumulate (prefetched sequential edge walk)
    float ssum = 0.f;
    int s_pf = csr[lo];               // deg >= 1 (self loop)
    float a_pf = as_[s_pf];

    if constexpr (D == 64) {
        float2 acc = make_float2(0.f, 0.f);
        for (int e = lo; e < hi; e++) {
            int s = s_pf;
            float av = a_pf;
            if (e + 1 < hi) { s_pf = csr[e + 1]; a_pf = as_[s_pf]; }
            float v = av + adv;
            v = (v > 0.f) ? v : 0.2f * v;
            float wgt = __expf(v - mx);
            ssum += wgt;
            float2 hv = *(const float2*)(h + (size_t)s * 64 + lane * 2);
            acc.x += wgt * hv.x;
            acc.y += wgt * hv.y;
        }
        float inv = 1.f / ssum;
        float2 bv = *(const float2*)(bias + lane * 2);
        float2 r;
        r.x = fmaxf(acc.x * inv + bv.x, 0.f);
        r.y = fmaxf(acc.y * inv + bv.y, 0.f);
        *(float2*)(out + (size_t)w * 64 + lane * 2) = r;
    } else {
        constexpr int NV = D / 128;   // float4 chunks per lane (1 or 2)
        float4 acc[NV];
#pragma unroll
        for (int k = 0; k < NV; k++) acc[k] = make_float4(0.f, 0.f, 0.f, 0.f);
        for (int e = lo; e < hi; e++) {
            int s = s_pf;
            float av = a_pf;
            if (e + 1 < hi) { s_pf = csr[e + 1]; a_pf = as_[s_pf]; }
            float v = av + adv;
            v = (v > 0.f) ? v : 0.2f * v;
            float wgt = __expf(v - mx);
            ssum += wgt;
            const float* hp = h + (size_t)s * D;
#pragma unroll
            for (int k = 0; k < NV; k++) {
                float4 hv = *(const float4*)(hp + lane * 4 + 128 * k);
                acc[k].x += wgt * hv.x;
                acc[k].y += wgt * hv.y;
                acc[k].z += wgt * hv.z;
                acc[k].w += wgt * hv.w;
            }
        }
        float inv = 1.f / ssum;
#pragma unroll
        for (int k = 0; k < NV; k++) {
            float4 bv = *(const float4*)(bias + lane * 4 + 128 * k);
            float4 r;
            r.x = fmaxf(acc[k].x * inv + bv.x, 0.f);
            r.y = fmaxf(acc[k].y * inv + bv.y, 0.f);
            r.z = fmaxf(acc[k].z * inv + bv.z, 0.f);
            r.w = fmaxf(acc[k].w * inv + bv.w, 0.f);
            *(float4*)(out + (size_t)w * D + lane * 4 + 128 * k) = r;
        }
    }
}

// ---------------- pooling + MLP ----------------
__device__ __forceinline__ int lbound(const int* a, int n, int key) {
    int lo = 0, hi = n;
    while (lo < hi) {
        int mid = (lo + hi) >> 1;
        if (a[mid] < key) lo = mid + 1; else hi = mid;
    }
    return lo;
}

__global__ void pool_mlp_kernel(const float* __restrict__ x, const int* __restrict__ batch,
                                const float* __restrict__ fc1w, const float* __restrict__ fc1b,
                                const float* __restrict__ fc2w, const float* __restrict__ fc2b,
                                float* __restrict__ out) {
    __shared__ float gc[DMAX];
    __shared__ float hid[HID];
    __shared__ float red[256];
    int g = blockIdx.x;
    int t = threadIdx.x;
    int lo = lbound(batch, NNODES, g);
    int hi = lbound(batch, NNODES, g + 1);
    float cnt = fmaxf((float)(hi - lo), 1.f);
    float acc = 0.f;
    for (int n = lo; n < hi; n++) acc += x[(size_t)n * DMAX + t];
    gc[t] = acc / cnt;
    __syncthreads();
    for (int c = t; c < HID; c += 256) {
        float a = fc1b[c];
#pragma unroll 8
        for (int k = 0; k < DMAX; k++) a += gc[k] * fc1w[(size_t)k * HID + c];
        hid[c] = fmaxf(a, 0.f);
    }
    __syncthreads();
    float p = 0.f;
    for (int c = t; c < HID; c += 256) p += hid[c] * fc2w[c];
    red[t] = p;
    __syncthreads();
    for (int s = 128; s; s >>= 1) {
        if (t < s) red[t] += red[t + s];
        __syncthreads();
    }
    if (t == 0) out[g] = red[0] + fc2b[0];
}

// ---------------- launcher ----------------
extern "C" void kernel_launch(void* const* d_in, const int* in_sizes, int n_in,
                              void* d_out, int out_size) {
    const float* feature = (const float*)d_in[0];
    const int*   ei      = (const int*)d_in[1];
    const int*   batch   = (const int*)d_in[2];
    const float* W[3]    = {(const float*)d_in[3], (const float*)d_in[6], (const float*)d_in[9]};
    const float* att[3]  = {(const float*)d_in[4], (const float*)d_in[7], (const float*)d_in[10]};
    const float* bia[3]  = {(const float*)d_in[5], (const float*)d_in[8], (const float*)d_in[11]};
    const float* fc1w    = (const float*)d_in[12];
    const float* fc1b    = (const float*)d_in[13];
    const float* fc2w    = (const float*)d_in[14];
    const float* fc2b    = (const float*)d_in[15];

    float *bufA, *bufC, *asbuf, *adbuf, *wabuf, *wdbuf;
    int *csr, *cnt, *off, *cursor, *bsum;
    cudaGetSymbolAddress((void**)&bufA, g_bufA);
    cudaGetSymbolAddress((void**)&bufC, g_bufC);
    cudaGetSymbolAddress((void**)&csr, g_csr);
    cudaGetSymbolAddress((void**)&cnt, g_cnt);
    cudaGetSymbolAddress((void**)&off, g_off);
    cudaGetSymbolAddress((void**)&cursor, g_cursor);
    cudaGetSymbolAddress((void**)&bsum, g_bsum);
    cudaGetSymbolAddress((void**)&asbuf, g_as);
    cudaGetSymbolAddress((void**)&adbuf, g_ad);
    cudaGetSymbolAddress((void**)&wabuf, g_wa);
    cudaGetSymbolAddress((void**)&wdbuf, g_wd);

    // ---- build CSR (by dst), once ----
    zero_cnt_kernel<<<NB, 256>>>(cnt);
    hist_kernel<<<(NEALL + 255) / 256, 256>>>(ei, cnt);
    scan1_kernel<<<NB, 256>>>(cnt, off, bsum);
    scan2_kernel<<<1, 256>>>(bsum);
    scan3_kernel<<<NB, 256>>>(off, bsum, cursor);
    csr_fill_kernel<<<(NEALL + 255) / 256, 256>>>(ei, cursor, csr);

    const int DinA[3]  = {64, 64, 128};
    const int DoutA[3] = {64, 128, 256};
    const float* x = feature;

    for (int l = 0; l < 3; l++) {
        int Din = DinA[l], D = DoutA[l];

        wvec_kernel<<<(Din * 2 * 32 + 255) / 256, 256>>>(W[l], att[l], Din, D, wabuf, wdbuf);
        attdot_x_kernel<<<(NNODES * 32 + 255) / 256, 256>>>(x, wabuf, wdbuf, Din, asbuf, adbuf);
        sgemm_kernel<<<dim3((NNODES + GBM - 1) / GBM, D / GBN), 256>>>(x, W[l], bufA, NNODES, D, Din);

        int aggBlocks = (NNODES * 32 + 255) / 256;
        if (D == 64)
            gat_aggregate_kernel<64><<<aggBlocks, 256>>>(bufA, asbuf, adbuf, off, csr, bia[l], bufC);
        else if (D == 128)
            gat_aggregate_kernel<128><<<aggBlocks, 256>>>(bufA, asbuf, adbuf, off, csr, bia[l], bufC);
        else
            gat_aggregate_kernel<256><<<aggBlocks, 256>>>(bufA, asbuf, adbuf, off, csr, bia[l], bufC);

        x = bufC;
    }

    pool_mlp_kernel<<<NGRAPH, 256>>>(bufC, batch, fc1w, fc1b, fc2w, fc2b, (float*)d_out);
}